// round 12
// baseline (speedup 1.0000x reference)
#include <cuda_runtime.h>
#include <cuda_bf16.h>
#include <cstdint>

// Problem constants
#define BATCH   8192
#define IN_DIM  256
#define HID_DIM 16384
#define OUT_DIM 256
#define TOPK    256

// ---------------------------------------------------------------------------
// Device scratch (no allocations allowed)
// ---------------------------------------------------------------------------
__device__ float g_dwt[(size_t)HID_DIM * OUT_DIM];                      // dec_w^T
__device__ __align__(256) __nv_bfloat16 g_xs[2][(size_t)BATCH * IN_DIM];   // x splits
__device__ __align__(256) __nv_bfloat16 g_ws[2][(size_t)HID_DIM * IN_DIM]; // w splits

// ---------------------------------------------------------------------------
// Portable PTX helpers (plain sm_103 target: sm_80+ baseline only)
// ---------------------------------------------------------------------------
__device__ __forceinline__ uint32_t smem_to_u32(const void* p) {
    uint32_t a;
    asm("{ .reg .u64 t; cvta.to.shared.u64 t, %1; cvt.u32.u64 %0, t; }"
        : "=r"(a) : "l"(p));
    return a;
}

#define CP_ASYNC16(dst_u32, src_ptr) \
    asm volatile("cp.async.cg.shared.global [%0], [%1], 16;" \
                 :: "r"(dst_u32), "l"(src_ptr) : "memory")
#define CP_COMMIT()  asm volatile("cp.async.commit_group;" ::: "memory")
#define CP_WAIT(N)   asm volatile("cp.async.wait_group %0;" :: "n"(N) : "memory")

#define LDSM_X4(r, addr) \
    asm volatile("ldmatrix.sync.aligned.m8n8.x4.shared.b16 {%0,%1,%2,%3}, [%4];" \
                 : "=r"((r)[0]), "=r"((r)[1]), "=r"((r)[2]), "=r"((r)[3]) \
                 : "r"(addr))
#define LDSM_X2(r, addr) \
    asm volatile("ldmatrix.sync.aligned.m8n8.x2.shared.b16 {%0,%1}, [%2];" \
                 : "=r"((r)[0]), "=r"((r)[1]) : "r"(addr))

// D(16x8,f32) += A(16x16,bf16,row) * B(16x8,bf16,col)
#define MMA_BF16(d, a, b) \
    asm volatile("mma.sync.aligned.m16n8k16.row.col.f32.bf16.bf16.f32 " \
                 "{%0,%1,%2,%3}, {%4,%5,%6,%7}, {%8,%9}, {%0,%1,%2,%3};" \
                 : "+f"((d)[0]), "+f"((d)[1]), "+f"((d)[2]), "+f"((d)[3]) \
                 : "r"((a)[0]), "r"((a)[1]), "r"((a)[2]), "r"((a)[3]), \
                   "r"((b)[0]), "r"((b)[1]))

// ---------------------------------------------------------------------------
// Split kernels: fp32 -> 2 bf16 components; GEMM uses 3 cross products.
// |h_noisy - h_exact| ~ 4e-6 << DELTA/2; decisions fixed by exact band.
// ---------------------------------------------------------------------------
__global__ void split_x_kernel(const float* __restrict__ src) {
    int i = blockIdx.x * blockDim.x + threadIdx.x;
    if (i >= BATCH * IN_DIM) return;
    float v = src[i];
    __nv_bfloat16 b0 = __float2bfloat16(v);
    __nv_bfloat16 b1 = __float2bfloat16(v - __bfloat162float(b0));
    g_xs[0][i] = b0; g_xs[1][i] = b1;
}

__global__ void split_w_kernel(const float* __restrict__ src) {
    int i = blockIdx.x * blockDim.x + threadIdx.x;
    if (i >= HID_DIM * IN_DIM) return;
    float v = src[i];
    __nv_bfloat16 b0 = __float2bfloat16(v);
    __nv_bfloat16 b1 = __float2bfloat16(v - __bfloat162float(b0));
    g_ws[0][i] = b0; g_ws[1][i] = b1;
}

// ---------------------------------------------------------------------------
// Kernel 0: transpose dec_w (OUT x HID) -> g_dwt (HID x OUT)
// ---------------------------------------------------------------------------
__global__ void transpose_kernel(const float* __restrict__ dw) {
    __shared__ float tile[32][33];
    const int n0 = blockIdx.x * 32;
    const int o0 = blockIdx.y * 32;
    const int tx = threadIdx.x;
    const int ty = threadIdx.y;
#pragma unroll
    for (int j = 0; j < 4; j++) {
        tile[ty + j * 8][tx] =
            dw[(size_t)(o0 + ty + j * 8) * HID_DIM + n0 + tx];
    }
    __syncthreads();
#pragma unroll
    for (int j = 0; j < 4; j++) {
        g_dwt[(size_t)(n0 + ty + j * 8) * OUT_DIM + o0 + tx] =
            tile[tx][ty + j * 8];
    }
}

// ---------------------------------------------------------------------------
// Kernel 1: HMMA bf16 2-split / 3-product GEMM
// 128x128 CTA, 8 warps (32x64), K in 8 chunks of 32, cp.async double buffer,
// 2 CTAs/SM (82KB smem).
// ---------------------------------------------------------------------------
#define STRIDE_B     80                         // 32 bf16 = 64B + 16B pad
#define PLANE_BYTES  (128 * STRIDE_B)           // 10240
#define BUF_BYTES    (4 * PLANE_BYTES)          // 40960
#define GEMM_SMEM    (2 * BUF_BYTES)            // 81920

__global__ __launch_bounds__(256, 2)
void gemm_mma_kernel(const float* __restrict__ bias, float* __restrict__ C) {
    extern __shared__ unsigned char smem[];
    const uint32_t sb = smem_to_u32(smem);
    const int t = threadIdx.x;
    const int wid = t >> 5;
    const int lane = t & 31;
    const int bm = blockIdx.y * 128;
    const int bn = blockIdx.x * 128;
    const int m0 = (wid & 3) * 32;              // warp row base within tile
    const int n0 = (wid >> 2) * 64;             // warp col base within tile

    const __nv_bfloat16* planes[4] = {
        g_xs[0] + (size_t)bm * IN_DIM, g_xs[1] + (size_t)bm * IN_DIM,
        g_ws[0] + (size_t)bn * IN_DIM, g_ws[1] + (size_t)bn * IN_DIM };

    float acc[2][8][4];
#pragma unroll
    for (int mt = 0; mt < 2; mt++)
#pragma unroll
        for (int nt = 0; nt < 8; nt++)
#pragma unroll
            for (int i = 0; i < 4; i++) acc[mt][nt][i] = 0.0f;

    // 4 planes x 128 rows x 64B per chunk
    auto load_chunk = [&](int buf, int c) {
#pragma unroll
        for (int p = 0; p < 4; p++) {
            const unsigned char* srcp = (const unsigned char*)planes[p];
#pragma unroll
            for (int i = 0; i < 2; i++) {
                int g = i * 256 + t;            // 0..511 16B units
                int row = g >> 2;               // 4 segs per row
                int seg = g & 3;
                const unsigned char* src =
                    srcp + ((size_t)row * IN_DIM + c * 32 + seg * 8) * 2;
                uint32_t dst = sb + buf * BUF_BYTES + p * PLANE_BYTES +
                               row * STRIDE_B + seg * 16;
                CP_ASYNC16(dst, src);
            }
        }
        CP_COMMIT();
    };

    auto compute_chunk = [&](int buf) {
        const uint32_t ab = sb + buf * BUF_BYTES;
#pragma unroll
        for (int j = 0; j < 2; j++) {           // k-steps of 16
            uint32_t af[2][2][4];
#pragma unroll
            for (int ap = 0; ap < 2; ap++)
#pragma unroll
                for (int mt = 0; mt < 2; mt++) {
                    uint32_t addr = ab + ap * PLANE_BYTES +
                        (uint32_t)(m0 + 16 * mt + (lane & 15)) * STRIDE_B +
                        j * 32 + (lane >> 4) * 16;
                    LDSM_X4(af[ap][mt], addr);
                }
#pragma unroll
            for (int bp = 0; bp < 2; bp++) {
                uint32_t bf[8][2];
                const int l = lane & 15;
#pragma unroll
                for (int nt = 0; nt < 8; nt++) {
                    uint32_t addr = ab + (2 + bp) * PLANE_BYTES +
                        (uint32_t)(n0 + 8 * nt + (l & 7)) * STRIDE_B +
                        j * 32 + (l >> 3) * 16;
                    LDSM_X2(bf[nt], addr);
                }
                const int na = (bp == 0) ? 2 : 1;   // (a0,b0)(a1,b0);(a0,b1)
#pragma unroll
                for (int ap = 0; ap < 2; ap++) {
                    if (ap >= na) break;
#pragma unroll
                    for (int mt = 0; mt < 2; mt++)
#pragma unroll
                        for (int nt = 0; nt < 8; nt++)
                            MMA_BF16(acc[mt][nt], af[ap][mt], bf[nt]);
                }
            }
        }
    };

    load_chunk(0, 0);
    load_chunk(1, 1);
#pragma unroll 1
    for (int kc = 0; kc < 6; kc++) {
        CP_WAIT(1); __syncthreads();
        compute_chunk(kc & 1);
        __syncthreads();
        load_chunk(kc & 1, kc + 2);
    }
    CP_WAIT(1); __syncthreads();
    compute_chunk(0);
    CP_WAIT(0); __syncthreads();
    compute_chunk(1);

    // ---- epilogue: + bias, relu, store
#pragma unroll
    for (int mt = 0; mt < 2; mt++) {
        const int r0 = bm + m0 + 16 * mt + (lane >> 2);
#pragma unroll
        for (int nt = 0; nt < 8; nt++) {
            const int col = bn + n0 + 8 * nt + 2 * (lane & 3);
            const float bv0 = __ldg(bias + col);
            const float bv1 = __ldg(bias + col + 1);
            float2 v0, v1;
            v0.x = fmaxf(acc[mt][nt][0] + bv0, 0.0f);
            v0.y = fmaxf(acc[mt][nt][1] + bv1, 0.0f);
            v1.x = fmaxf(acc[mt][nt][2] + bv0, 0.0f);
            v1.y = fmaxf(acc[mt][nt][3] + bv1, 0.0f);
            *(float2*)&C[(size_t)r0 * HID_DIM + col] = v0;
            *(float2*)&C[(size_t)(r0 + 8) * HID_DIM + col] = v1;
        }
    }
}

// ---------------------------------------------------------------------------
// Kernel 2 (fused v3): compact {v >= PIVOT} -> register-resident bitwise
// select of exact k-th largest -> list-based classification + exact band
// recheck -> zero-fill + scatter writeback -> sparse decode.
// One CTA (256 threads) per row.  ~55KB smem -> 4 CTAs/SM.
// Atomic-free threshold selection (pure ALU + block reduces).
// ---------------------------------------------------------------------------
#define DELTA     1e-2f
#define PIVOT     0.5f
#define LIST_CAP  5888
#define BAND_CAP  256
#define KEEP_CAP  512

struct FusedSmem {
    float  list_v[LIST_CAP];      // 23KB
    int    list_i[LIST_CAP];      // 23KB
    float  x_row[IN_DIM];         //  1KB
    float  band_exact[BAND_CAP];  //  1KB
    int    band_idx[BAND_CAP];    //  1KB
    int    band_keep[BAND_CAP];   //  1KB
    float  kvals[KEEP_CAP];       //  2KB
    int    kidxs[KEEP_CAP];       //  2KB
    int    red[8];
    int    sh_i;
    int    cnt_list, band_cnt, keep_cnt;
};

__global__ __launch_bounds__(256)
void fused_topk_decode_kernel(float* __restrict__ hid,
                              const float* __restrict__ x,
                              const float* __restrict__ enc_w,
                              const float* __restrict__ enc_b,
                              const float* __restrict__ dec_b,
                              float* __restrict__ out) {
    extern __shared__ unsigned char smem_raw[];
    FusedSmem& s = *reinterpret_cast<FusedSmem*>(smem_raw);

    const int t = threadIdx.x;            // 0..255
    const int wid = t >> 5;
    const int lane = t & 31;
    const int row = blockIdx.x;
    float* hrow = hid + (size_t)row * HID_DIM;
    const float4* hrow4 = (const float4*)hrow;

    // block-wide int sum (uniform call sites only)
    auto breduce = [&](int v) -> int {
#pragma unroll
        for (int off = 16; off; off >>= 1)
            v += __shfl_xor_sync(0xFFFFFFFFu, v, off);
        if (lane == 0) s.red[wid] = v;
        __syncthreads();
        if (wid == 0) {
            int xv = (lane < 8) ? s.red[lane] : 0;
#pragma unroll
            for (int off = 4; off; off >>= 1)
                xv += __shfl_xor_sync(0xFFFFFFFFu, xv, off);
            if (lane == 0) s.sh_i = xv;
        }
        __syncthreads();
        return s.sh_i;
    };

    s.x_row[t] = x[(size_t)row * IN_DIM + t];
    if (t == 0) { s.cnt_list = 0; s.band_cnt = 0; s.keep_cnt = 0; }
    __syncthreads();

    // ---- Pass 1 (single DRAM read): compact (val, idx) of {v >= PIVOT}
#pragma unroll 2
    for (int i = 0; i < 16; i++) {
        float4 v4 = hrow4[i * 256 + t];
        float vv[4] = { v4.x, v4.y, v4.z, v4.w };
#pragma unroll
        for (int c = 0; c < 4; c++) {
            float v = vv[c];
            bool q = (v >= PIVOT);
            unsigned int m = __ballot_sync(0xFFFFFFFFu, q);
            if (q) {
                int leader = __ffs(m) - 1;
                int base;
                if (lane == leader) base = atomicAdd(&s.cnt_list, __popc(m));
                base = __shfl_sync(m, base, leader);
                int pos = base + __popc(m & ((1u << lane) - 1u));
                if (pos < LIST_CAP) {
                    s.list_v[pos] = v;
                    s.list_i[pos] = (i * 256 + t) * 4 + c;
                }
            }
        }
    }
    __syncthreads();
    const int raw_cnt = s.cnt_list;
    const int nl = min(raw_cnt, LIST_CAP);
    bool fast = (raw_cnt <= LIST_CAP) && (raw_cnt >= TOPK);

    float thr;
    if (fast) {
        // ---- exact k-th largest via bitwise binary search (registers)
        unsigned int keys[23];
        int nk = 0;
        for (int j = t; j < nl; j += 256)
            keys[nk++] = __float_as_uint(s.list_v[j]);
        unsigned int prefix = 0;
#pragma unroll 1
        for (int b = 31; b >= 0; b--) {
            unsigned int trial = prefix | (1u << b);
            int c = 0;
#pragma unroll 1
            for (int j = 0; j < nk; j++)
                c += (keys[j] >= trial) ? 1 : 0;
            if (breduce(c) >= TOPK) prefix = trial;
        }
        thr = __uint_as_float(prefix);
        if (thr < PIVOT + DELTA) fast = false;   // band could dip below PIVOT
    }

    if (!fast) {
        // ---- general fallback: bitwise search over gmem (never taken here)
        unsigned int prefix = 0;
#pragma unroll 1
        for (int b = 31; b >= 0; b--) {
            unsigned int trial = prefix | (1u << b);
            int c = 0;
            for (int i = 0; i < 16; i++) {
                float4 v4 = hrow4[i * 256 + t];
                c += (__float_as_uint(v4.x) >= trial) ? 1 : 0;
                c += (__float_as_uint(v4.y) >= trial) ? 1 : 0;
                c += (__float_as_uint(v4.z) >= trial) ? 1 : 0;
                c += (__float_as_uint(v4.w) >= trial) ? 1 : 0;
            }
            if (breduce(c) >= TOPK) prefix = trial;
        }
        thr = __uint_as_float(prefix);
        if (prefix == 0u) {
            // thr == 0: reference keeps everything; hidden_post == h (in place)
            float acc = 0.0f;
            for (int j = 0; j < HID_DIM; j++) {
                float v = __ldg(hrow + j);
                if (v != 0.0f)
                    acc = fmaf(v, g_dwt[(size_t)j * OUT_DIM + t], acc);
            }
            out[(size_t)row * OUT_DIM + t] = acc + dec_b[t];
            return;
        }
    }
    const float thr_hi = thr + DELTA;
    const float thr_lo = thr - DELTA;

    // ---- classification: sure-keeps -> keep list; band -> band list
    int my_hi = 0;
    if (fast) {
        for (int j = t; j < nl; j += 256) {
            float v = s.list_v[j];
            if (v > thr_hi) {
                my_hi++;
                int p = atomicAdd(&s.keep_cnt, 1);
                if (p < KEEP_CAP) { s.kvals[p] = v; s.kidxs[p] = s.list_i[j]; }
            } else if (v >= thr_lo) {
                int p = atomicAdd(&s.band_cnt, 1);
                if (p < BAND_CAP) s.band_idx[p] = s.list_i[j];
            }
        }
    } else {
        for (int i = 0; i < 16; i++) {
            float4 v4 = hrow4[i * 256 + t];
            float vv[4] = { v4.x, v4.y, v4.z, v4.w };
            for (int c = 0; c < 4; c++) {
                float v = vv[c];
                int n = (i * 256 + t) * 4 + c;
                if (v > thr_hi) {
                    my_hi++;
                    int p = atomicAdd(&s.keep_cnt, 1);
                    if (p < KEEP_CAP) { s.kvals[p] = v; s.kidxs[p] = n; }
                } else if (v >= thr_lo) {
                    int p = atomicAdd(&s.band_cnt, 1);
                    if (p < BAND_CAP) s.band_idx[p] = n;
                }
            }
        }
    }
    const int n_hi = breduce(my_hi);
    const int bc = min(s.band_cnt, BAND_CAP);

    // ---- exact fp32 recompute of band candidates (one warp per candidate)
    for (int b = wid; b < bc; b += 8) {
        const int n = s.band_idx[b];
        const float* wrow = enc_w + (size_t)n * IN_DIM;
        float4 xa = *(const float4*)&s.x_row[lane * 8];
        float4 xb = *(const float4*)&s.x_row[lane * 8 + 4];
        float4 wa = *(const float4*)&wrow[lane * 8];
        float4 wb = *(const float4*)&wrow[lane * 8 + 4];
        float p = xa.x * wa.x;
        p = fmaf(xa.y, wa.y, p);
        p = fmaf(xa.z, wa.z, p);
        p = fmaf(xa.w, wa.w, p);
        p = fmaf(xb.x, wb.x, p);
        p = fmaf(xb.y, wb.y, p);
        p = fmaf(xb.z, wb.z, p);
        p = fmaf(xb.w, wb.w, p);
#pragma unroll
        for (int off = 16; off; off >>= 1)
            p += __shfl_xor_sync(0xFFFFFFFFu, p, off);
        if (lane == 0)
            s.band_exact[b] = fmaxf(p + __ldg(enc_b + n), 0.0f);
    }
    __syncthreads();

    // ---- keep top (TOPK - n_hi) band values by exact value, >= ties kept
    if (wid == 0) {
        const int kr = TOPK - n_hi;   // >= 1 by construction
        for (int i = lane; i < bc; i += 32) {
            float ei = s.band_exact[i];
            int cnt = 0;
            for (int j = 0; j < bc; j++)
                cnt += (s.band_exact[j] > ei) ? 1 : 0;
            s.band_keep[i] = (cnt < kr) ? 1 : 0;
        }
    }
    __syncthreads();
    for (int b = t; b < bc; b += 256) {
        if (s.band_keep[b]) {
            int p = atomicAdd(&s.keep_cnt, 1);
            if (p < KEEP_CAP) {
                s.kvals[p] = s.band_exact[b];
                s.kidxs[p] = s.band_idx[b];
            }
        }
    }
    __syncthreads();
    const int m = min(s.keep_cnt, KEEP_CAP);

    // ---- writeback: zero-fill row (no read), then scatter the keeps
    {
        float4 z = make_float4(0.0f, 0.0f, 0.0f, 0.0f);
        float4* w4 = (float4*)hrow;
#pragma unroll 4
        for (int i = 0; i < 16; i++) w4[i * 256 + t] = z;
    }
    __syncthreads();
    for (int j = t; j < m; j += 256) hrow[s.kidxs[j]] = s.kvals[j];

    // ---- sparse decode over compacted keeps
    float acc = 0.0f;
#pragma unroll 8
    for (int j = 0; j < m; j++) {
        acc = fmaf(s.kvals[j], g_dwt[(size_t)s.kidxs[j] * OUT_DIM + t], acc);
    }
    out[(size_t)row * OUT_DIM + t] = acc + dec_b[t];
}

// ---------------------------------------------------------------------------
// kernel_launch
//   inputs: 0=x, 1=enc_w, 2=enc_b, 3=dec_w, 4=dec_b, 5=k (fixed 256)
//   output: [output (8192*256) | hidden_post (8192*16384)] fp32
// ---------------------------------------------------------------------------
extern "C" void kernel_launch(void* const* d_in, const int* in_sizes, int n_in,
                              void* d_out, int out_size) {
    const float* x     = (const float*)d_in[0];
    const float* enc_w = (const float*)d_in[1];
    const float* enc_b = (const float*)d_in[2];
    const float* dec_w = (const float*)d_in[3];
    const float* dec_b = (const float*)d_in[4];

    float* out = (float*)d_out;
    float* hid = out + (size_t)BATCH * OUT_DIM;

    // idempotent attribute setup (host-side, not captured)
    cudaFuncSetAttribute(fused_topk_decode_kernel,
                         cudaFuncAttributeMaxDynamicSharedMemorySize,
                         (int)sizeof(FusedSmem));
    cudaFuncSetAttribute(gemm_mma_kernel,
                         cudaFuncAttributeMaxDynamicSharedMemorySize,
                         GEMM_SMEM);

    // prep: 2-way bf16 splits of x and enc_w; dec_w transpose
    split_x_kernel<<<(BATCH * IN_DIM + 255) / 256, 256>>>(x);
    split_w_kernel<<<(HID_DIM * IN_DIM + 255) / 256, 256>>>(enc_w);
    transpose_kernel<<<dim3(HID_DIM / 32, OUT_DIM / 32), dim3(32, 8)>>>(dec_w);

    // k1: HMMA bf16 2-split / 3-product encoder GEMM + bias + relu
    gemm_mma_kernel<<<dim3(HID_DIM / 128, BATCH / 128), 256, GEMM_SMEM>>>(enc_b, hid);

    // k2: fused top-k (atomic-free exact select) + band recheck + decode
    fused_topk_decode_kernel<<<BATCH, 256, sizeof(FusedSmem)>>>(
        hid, x, enc_w, enc_b, dec_b, out);
}

// round 14
// speedup vs baseline: 1.2872x; 1.2872x over previous
#include <cuda_runtime.h>
#include <cuda_bf16.h>
#include <cstdint>

// Problem constants
#define BATCH   8192
#define IN_DIM  256
#define HID_DIM 16384
#define OUT_DIM 256
#define TOPK    256

// ---------------------------------------------------------------------------
// Device scratch (no allocations allowed)
// ---------------------------------------------------------------------------
__device__ float g_dwt[(size_t)HID_DIM * OUT_DIM];                      // dec_w^T
__device__ __align__(256) __nv_bfloat16 g_xs[2][(size_t)BATCH * IN_DIM];   // x splits
__device__ __align__(256) __nv_bfloat16 g_ws[2][(size_t)HID_DIM * IN_DIM]; // w splits

// ---------------------------------------------------------------------------
// Portable PTX helpers (plain sm_103 target: sm_80+ baseline only)
// ---------------------------------------------------------------------------
__device__ __forceinline__ uint32_t smem_to_u32(const void* p) {
    uint32_t a;
    asm("{ .reg .u64 t; cvta.to.shared.u64 t, %1; cvt.u32.u64 %0, t; }"
        : "=r"(a) : "l"(p));
    return a;
}

#define CP_ASYNC16(dst_u32, src_ptr) \
    asm volatile("cp.async.cg.shared.global [%0], [%1], 16;" \
                 :: "r"(dst_u32), "l"(src_ptr) : "memory")
#define CP_COMMIT()  asm volatile("cp.async.commit_group;" ::: "memory")
#define CP_WAIT(N)   asm volatile("cp.async.wait_group %0;" :: "n"(N) : "memory")

#define LDSM_X4(r, addr) \
    asm volatile("ldmatrix.sync.aligned.m8n8.x4.shared.b16 {%0,%1,%2,%3}, [%4];" \
                 : "=r"((r)[0]), "=r"((r)[1]), "=r"((r)[2]), "=r"((r)[3]) \
                 : "r"(addr))
#define LDSM_X2(r, addr) \
    asm volatile("ldmatrix.sync.aligned.m8n8.x2.shared.b16 {%0,%1}, [%2];" \
                 : "=r"((r)[0]), "=r"((r)[1]) : "r"(addr))

// D(16x8,f32) += A(16x16,bf16,row) * B(16x8,bf16,col)
#define MMA_BF16(d, a, b) \
    asm volatile("mma.sync.aligned.m16n8k16.row.col.f32.bf16.bf16.f32 " \
                 "{%0,%1,%2,%3}, {%4,%5,%6,%7}, {%8,%9}, {%0,%1,%2,%3};" \
                 : "+f"((d)[0]), "+f"((d)[1]), "+f"((d)[2]), "+f"((d)[3]) \
                 : "r"((a)[0]), "r"((a)[1]), "r"((a)[2]), "r"((a)[3]), \
                   "r"((b)[0]), "r"((b)[1]))

// ---------------------------------------------------------------------------
// Split kernels: fp32 -> 2 bf16 components; GEMM uses 3 cross products.
// |h_noisy - h_exact| ~ 4e-6 << DELTA/2; decisions fixed by exact band.
// ---------------------------------------------------------------------------
__global__ void split_x_kernel(const float* __restrict__ src) {
    int i = blockIdx.x * blockDim.x + threadIdx.x;
    if (i >= BATCH * IN_DIM) return;
    float v = src[i];
    __nv_bfloat16 b0 = __float2bfloat16(v);
    __nv_bfloat16 b1 = __float2bfloat16(v - __bfloat162float(b0));
    g_xs[0][i] = b0; g_xs[1][i] = b1;
}

__global__ void split_w_kernel(const float* __restrict__ src) {
    int i = blockIdx.x * blockDim.x + threadIdx.x;
    if (i >= HID_DIM * IN_DIM) return;
    float v = src[i];
    __nv_bfloat16 b0 = __float2bfloat16(v);
    __nv_bfloat16 b1 = __float2bfloat16(v - __bfloat162float(b0));
    g_ws[0][i] = b0; g_ws[1][i] = b1;
}

// ---------------------------------------------------------------------------
// Kernel 0: transpose dec_w (OUT x HID) -> g_dwt (HID x OUT)
// ---------------------------------------------------------------------------
__global__ void transpose_kernel(const float* __restrict__ dw) {
    __shared__ float tile[32][33];
    const int n0 = blockIdx.x * 32;
    const int o0 = blockIdx.y * 32;
    const int tx = threadIdx.x;
    const int ty = threadIdx.y;
#pragma unroll
    for (int j = 0; j < 4; j++) {
        tile[ty + j * 8][tx] =
            dw[(size_t)(o0 + ty + j * 8) * HID_DIM + n0 + tx];
    }
    __syncthreads();
#pragma unroll
    for (int j = 0; j < 4; j++) {
        g_dwt[(size_t)(n0 + ty + j * 8) * OUT_DIM + o0 + tx] =
            tile[tx][ty + j * 8];
    }
}

// ---------------------------------------------------------------------------
// Kernel 1: HMMA bf16 2-split / 3-product GEMM  (unchanged from R12: 567us)
// 128x128 CTA, 8 warps (32x64), K in 8 chunks of 32, cp.async double buffer,
// 2 CTAs/SM (82KB smem).
// ---------------------------------------------------------------------------
#define STRIDE_B     80                         // 32 bf16 = 64B + 16B pad
#define PLANE_BYTES  (128 * STRIDE_B)           // 10240
#define BUF_BYTES    (4 * PLANE_BYTES)          // 40960
#define GEMM_SMEM    (2 * BUF_BYTES)            // 81920

__global__ __launch_bounds__(256, 2)
void gemm_mma_kernel(const float* __restrict__ bias, float* __restrict__ C) {
    extern __shared__ unsigned char smem[];
    const uint32_t sb = smem_to_u32(smem);
    const int t = threadIdx.x;
    const int wid = t >> 5;
    const int lane = t & 31;
    const int bm = blockIdx.y * 128;
    const int bn = blockIdx.x * 128;
    const int m0 = (wid & 3) * 32;              // warp row base within tile
    const int n0 = (wid >> 2) * 64;             // warp col base within tile

    const __nv_bfloat16* planes[4] = {
        g_xs[0] + (size_t)bm * IN_DIM, g_xs[1] + (size_t)bm * IN_DIM,
        g_ws[0] + (size_t)bn * IN_DIM, g_ws[1] + (size_t)bn * IN_DIM };

    float acc[2][8][4];
#pragma unroll
    for (int mt = 0; mt < 2; mt++)
#pragma unroll
        for (int nt = 0; nt < 8; nt++)
#pragma unroll
            for (int i = 0; i < 4; i++) acc[mt][nt][i] = 0.0f;

    auto load_chunk = [&](int buf, int c) {
#pragma unroll
        for (int p = 0; p < 4; p++) {
            const unsigned char* srcp = (const unsigned char*)planes[p];
#pragma unroll
            for (int i = 0; i < 2; i++) {
                int g = i * 256 + t;            // 0..511 16B units
                int row = g >> 2;               // 4 segs per row
                int seg = g & 3;
                const unsigned char* src =
                    srcp + ((size_t)row * IN_DIM + c * 32 + seg * 8) * 2;
                uint32_t dst = sb + buf * BUF_BYTES + p * PLANE_BYTES +
                               row * STRIDE_B + seg * 16;
                CP_ASYNC16(dst, src);
            }
        }
        CP_COMMIT();
    };

    auto compute_chunk = [&](int buf) {
        const uint32_t ab = sb + buf * BUF_BYTES;
#pragma unroll
        for (int j = 0; j < 2; j++) {           // k-steps of 16
            uint32_t af[2][2][4];
#pragma unroll
            for (int ap = 0; ap < 2; ap++)
#pragma unroll
                for (int mt = 0; mt < 2; mt++) {
                    uint32_t addr = ab + ap * PLANE_BYTES +
                        (uint32_t)(m0 + 16 * mt + (lane & 15)) * STRIDE_B +
                        j * 32 + (lane >> 4) * 16;
                    LDSM_X4(af[ap][mt], addr);
                }
#pragma unroll
            for (int bp = 0; bp < 2; bp++) {
                uint32_t bf[8][2];
                const int l = lane & 15;
#pragma unroll
                for (int nt = 0; nt < 8; nt++) {
                    uint32_t addr = ab + (2 + bp) * PLANE_BYTES +
                        (uint32_t)(n0 + 8 * nt + (l & 7)) * STRIDE_B +
                        j * 32 + (l >> 3) * 16;
                    LDSM_X2(bf[nt], addr);
                }
                const int na = (bp == 0) ? 2 : 1;   // (a0,b0)(a1,b0);(a0,b1)
#pragma unroll
                for (int ap = 0; ap < 2; ap++) {
                    if (ap >= na) break;
#pragma unroll
                    for (int mt = 0; mt < 2; mt++)
#pragma unroll
                        for (int nt = 0; nt < 8; nt++)
                            MMA_BF16(acc[mt][nt], af[ap][mt], bf[nt]);
                }
            }
        }
    };

    load_chunk(0, 0);
    load_chunk(1, 1);
#pragma unroll 1
    for (int kc = 0; kc < 6; kc++) {
        CP_WAIT(1); __syncthreads();
        compute_chunk(kc & 1);
        __syncthreads();
        load_chunk(kc & 1, kc + 2);
    }
    CP_WAIT(1); __syncthreads();
    compute_chunk(0);
    CP_WAIT(0); __syncthreads();
    compute_chunk(1);

    // ---- epilogue: + bias, relu, store
#pragma unroll
    for (int mt = 0; mt < 2; mt++) {
        const int r0 = bm + m0 + 16 * mt + (lane >> 2);
#pragma unroll
        for (int nt = 0; nt < 8; nt++) {
            const int col = bn + n0 + 8 * nt + 2 * (lane & 3);
            const float bv0 = __ldg(bias + col);
            const float bv1 = __ldg(bias + col + 1);
            float2 v0, v1;
            v0.x = fmaxf(acc[mt][nt][0] + bv0, 0.0f);
            v0.y = fmaxf(acc[mt][nt][1] + bv1, 0.0f);
            v1.x = fmaxf(acc[mt][nt][2] + bv0, 0.0f);
            v1.y = fmaxf(acc[mt][nt][3] + bv1, 0.0f);
            *(float2*)&C[(size_t)r0 * HID_DIM + col] = v0;
            *(float2*)&C[(size_t)(r0 + 8) * HID_DIM + col] = v1;
        }
    }
}

// ---------------------------------------------------------------------------
// Kernel 2 (fused v4): single-read list compaction + HISTOGRAM radix select
// over the smem list (R10's proven engine, 12 barriers total) + exact band
// recheck + zero-fill/scatter writeback + sparse decode.
// One CTA (256 threads) per row; ~54KB smem -> 4 CTAs/SM.
// ---------------------------------------------------------------------------
#define DELTA     1e-2f
#define PIVOT     0.5f
#define LIST_CAP  5504
#define BAND_CAP  256
#define KEEP_CAP  512

struct FusedSmem {
    float  list_v[LIST_CAP];      // 21.5KB
    int    list_i[LIST_CAP];      // 21.5KB
    float  x_row[IN_DIM];         //  1KB
    unsigned int hist[256];       //  1KB
    float  band_exact[BAND_CAP];  //  1KB
    int    band_idx[BAND_CAP];    //  1KB
    int    band_keep[BAND_CAP];   //  1KB
    float  kvals[KEEP_CAP];       //  2KB
    int    kidxs[KEEP_CAP];       //  2KB
    int    red[8];
    int    sh_i;
    unsigned int sh_prefix;
    int    sh_krem;
    int    cnt_list, band_cnt, keep_cnt;
};

__global__ __launch_bounds__(256)
void fused_topk_decode_kernel(float* __restrict__ hid,
                              const float* __restrict__ x,
                              const float* __restrict__ enc_w,
                              const float* __restrict__ enc_b,
                              const float* __restrict__ dec_b,
                              float* __restrict__ out) {
    extern __shared__ unsigned char smem_raw[];
    FusedSmem& s = *reinterpret_cast<FusedSmem*>(smem_raw);

    const int t = threadIdx.x;            // 0..255
    const int wid = t >> 5;
    const int lane = t & 31;
    const int row = blockIdx.x;
    float* hrow = hid + (size_t)row * HID_DIM;
    const float4* hrow4 = (const float4*)hrow;

    auto breduce = [&](int v) -> int {    // block int sum (uniform sites)
#pragma unroll
        for (int off = 16; off; off >>= 1)
            v += __shfl_xor_sync(0xFFFFFFFFu, v, off);
        if (lane == 0) s.red[wid] = v;
        __syncthreads();
        if (wid == 0) {
            int xv = (lane < 8) ? s.red[lane] : 0;
#pragma unroll
            for (int off = 4; off; off >>= 1)
                xv += __shfl_xor_sync(0xFFFFFFFFu, xv, off);
            if (lane == 0) s.sh_i = xv;
        }
        __syncthreads();
        return s.sh_i;
    };

    s.x_row[t] = x[(size_t)row * IN_DIM + t];
    if (t == 0) { s.cnt_list = 0; s.band_cnt = 0; s.keep_cnt = 0; }
    __syncthreads();

    // ---- Pass 1 (single DRAM read): compact (val, idx) of {v >= PIVOT}
#pragma unroll 2
    for (int i = 0; i < 16; i++) {
        float4 v4 = hrow4[i * 256 + t];
        float vv[4] = { v4.x, v4.y, v4.z, v4.w };
#pragma unroll
        for (int c = 0; c < 4; c++) {
            float v = vv[c];
            bool q = (v >= PIVOT);
            unsigned int m = __ballot_sync(0xFFFFFFFFu, q);
            if (q) {
                int leader = __ffs(m) - 1;
                int base;
                if (lane == leader) base = atomicAdd(&s.cnt_list, __popc(m));
                base = __shfl_sync(m, base, leader);
                int pos = base + __popc(m & ((1u << lane) - 1u));
                if (pos < LIST_CAP) {
                    s.list_v[pos] = v;
                    s.list_i[pos] = (i * 256 + t) * 4 + c;
                }
            }
        }
    }
    __syncthreads();
    const int raw_cnt = s.cnt_list;
    const int nl = min(raw_cnt, LIST_CAP);
    bool fast = (raw_cnt <= LIST_CAP) && (raw_cnt >= TOPK);

    unsigned int prefix = 0, maskhi = 0;
    int krem = TOPK;
    float thr = 0.0f;

    if (fast) {
        // ---- 4-round histogram radix over the smem list (aggregated atomics)
        const int nlp = (nl + 255) & ~255;      // padded for full-warp collectives
#pragma unroll 1
        for (int r = 0; r < 4; r++) {
            const int shift = 24 - r * 8;
            s.hist[t] = 0;
            __syncthreads();
            for (int j = t; j < nlp; j += 256) {
                bool ok = (j < nl);
                unsigned int key = ok ? __float_as_uint(s.list_v[j]) : 0u;
                ok = ok && ((key & maskhi) == prefix);
                unsigned int bin = ok ? ((key >> shift) & 255u) : 0x1000u + lane;
                unsigned int grp = __match_any_sync(0xFFFFFFFFu, bin);
                if (ok && lane == (__ffs(grp) - 1))
                    atomicAdd(&s.hist[bin], (unsigned int)__popc(grp));
            }
            __syncthreads();
            if (t == 0) {
                unsigned int cum = 0;
                int d = 255;
                for (; d > 0; d--) {
                    unsigned int c = s.hist[d];
                    if (cum + c >= (unsigned int)krem) break;
                    cum += c;
                }
                s.sh_prefix = prefix | ((unsigned int)d << shift);
                s.sh_krem = krem - (int)cum;
            }
            __syncthreads();
            prefix = s.sh_prefix;
            krem = s.sh_krem;
            maskhi |= (0xFFu << shift);
        }
        thr = __uint_as_float(prefix);
        if (thr < PIVOT + DELTA) fast = false;  // band could dip below PIVOT
    }

    if (!fast) {
        // ---- general fallback: 4-round radix over gmem (never taken here)
        prefix = 0; maskhi = 0; krem = TOPK;
#pragma unroll 1
        for (int r = 0; r < 4; r++) {
            const int shift = 24 - r * 8;
            s.hist[t] = 0;
            __syncthreads();
#pragma unroll 1
            for (int i = 0; i < 16; i++) {
                float4 v4 = hrow4[i * 256 + t];
                unsigned int k4[4] = { __float_as_uint(v4.x), __float_as_uint(v4.y),
                                       __float_as_uint(v4.z), __float_as_uint(v4.w) };
#pragma unroll
                for (int c = 0; c < 4; c++) {
                    bool ok = ((k4[c] & maskhi) == prefix) && (k4[c] != 0u);
                    unsigned int bin = ok ? ((k4[c] >> shift) & 255u) : 0x1000u + lane;
                    unsigned int grp = __match_any_sync(0xFFFFFFFFu, bin);
                    if (ok && lane == (__ffs(grp) - 1))
                        atomicAdd(&s.hist[bin], (unsigned int)__popc(grp));
                }
            }
            __syncthreads();
            if (t == 0) {
                unsigned int cum = 0;
                int d = 255;
                for (; d > 0; d--) {
                    unsigned int c = s.hist[d];
                    if (cum + c >= (unsigned int)krem) break;
                    cum += c;
                }
                s.sh_prefix = prefix | ((unsigned int)d << shift);
                s.sh_krem = krem - (int)cum;
            }
            __syncthreads();
            prefix = s.sh_prefix;
            krem = s.sh_krem;
            maskhi |= (0xFFu << shift);
        }
        thr = __uint_as_float(prefix);
        if ((prefix & 0xFF000000u) == 0u) {
            // thr ~ 0: reference keeps everything; hidden_post == h (in place)
            float acc = 0.0f;
            for (int j = 0; j < HID_DIM; j++) {
                float v = __ldg(hrow + j);
                if (v != 0.0f)
                    acc = fmaf(v, g_dwt[(size_t)j * OUT_DIM + t], acc);
            }
            out[(size_t)row * OUT_DIM + t] = acc + dec_b[t];
            return;
        }
    }
    const float thr_hi = thr + DELTA;
    const float thr_lo = thr - DELTA;

    // ---- classification: sure-keeps -> keep list; band -> band list
    int my_hi = 0;
    if (fast) {
        for (int j = t; j < nl; j += 256) {
            float v = s.list_v[j];
            if (v > thr_hi) {
                my_hi++;
                int p = atomicAdd(&s.keep_cnt, 1);
                if (p < KEEP_CAP) { s.kvals[p] = v; s.kidxs[p] = s.list_i[j]; }
            } else if (v >= thr_lo) {
                int p = atomicAdd(&s.band_cnt, 1);
                if (p < BAND_CAP) s.band_idx[p] = s.list_i[j];
            }
        }
    } else {
        for (int i = 0; i < 16; i++) {
            float4 v4 = hrow4[i * 256 + t];
            float vv[4] = { v4.x, v4.y, v4.z, v4.w };
            for (int c = 0; c < 4; c++) {
                float v = vv[c];
                int n = (i * 256 + t) * 4 + c;
                if (v > thr_hi) {
                    my_hi++;
                    int p = atomicAdd(&s.keep_cnt, 1);
                    if (p < KEEP_CAP) { s.kvals[p] = v; s.kidxs[p] = n; }
                } else if (v >= thr_lo) {
                    int p = atomicAdd(&s.band_cnt, 1);
                    if (p < BAND_CAP) s.band_idx[p] = n;
                }
            }
        }
    }
    const int n_hi = breduce(my_hi);
    const int bc = min(s.band_cnt, BAND_CAP);

    // ---- exact fp32 recompute of band candidates (one warp per candidate)
    for (int b = wid; b < bc; b += 8) {
        const int n = s.band_idx[b];
        const float* wrow = enc_w + (size_t)n * IN_DIM;
        float4 xa = *(const float4*)&s.x_row[lane * 8];
        float4 xb = *(const float4*)&s.x_row[lane * 8 + 4];
        float4 wa = *(const float4*)&wrow[lane * 8];
        float4 wb = *(const float4*)&wrow[lane * 8 + 4];
        float p = xa.x * wa.x;
        p = fmaf(xa.y, wa.y, p);
        p = fmaf(xa.z, wa.z, p);
        p = fmaf(xa.w, wa.w, p);
        p = fmaf(xb.x, wb.x, p);
        p = fmaf(xb.y, wb.y, p);
        p = fmaf(xb.z, wb.z, p);
        p = fmaf(xb.w, wb.w, p);
#pragma unroll
        for (int off = 16; off; off >>= 1)
            p += __shfl_xor_sync(0xFFFFFFFFu, p, off);
        if (lane == 0)
            s.band_exact[b] = fmaxf(p + __ldg(enc_b + n), 0.0f);
    }
    __syncthreads();

    // ---- keep top (TOPK - n_hi) band values by exact value, >= ties kept
    if (wid == 0) {
        const int kr = TOPK - n_hi;   // >= 1 by construction
        for (int i = lane; i < bc; i += 32) {
            float ei = s.band_exact[i];
            int cnt = 0;
            for (int j = 0; j < bc; j++)
                cnt += (s.band_exact[j] > ei) ? 1 : 0;
            s.band_keep[i] = (cnt < kr) ? 1 : 0;
        }
    }
    __syncthreads();
    for (int b = t; b < bc; b += 256) {
        if (s.band_keep[b]) {
            int p = atomicAdd(&s.keep_cnt, 1);
            if (p < KEEP_CAP) {
                s.kvals[p] = s.band_exact[b];
                s.kidxs[p] = s.band_idx[b];
            }
        }
    }
    __syncthreads();
    const int m = min(s.keep_cnt, KEEP_CAP);

    // ---- writeback: zero-fill row (no read), then scatter the keeps
    {
        float4 z = make_float4(0.0f, 0.0f, 0.0f, 0.0f);
        float4* w4 = (float4*)hrow;
#pragma unroll 4
        for (int i = 0; i < 16; i++) w4[i * 256 + t] = z;
    }
    __syncthreads();
    for (int j = t; j < m; j += 256) hrow[s.kidxs[j]] = s.kvals[j];

    // ---- sparse decode over compacted keeps
    float acc = 0.0f;
#pragma unroll 8
    for (int j = 0; j < m; j++) {
        acc = fmaf(s.kvals[j], g_dwt[(size_t)s.kidxs[j] * OUT_DIM + t], acc);
    }
    out[(size_t)row * OUT_DIM + t] = acc + dec_b[t];
}

// ---------------------------------------------------------------------------
// kernel_launch
//   inputs: 0=x, 1=enc_w, 2=enc_b, 3=dec_w, 4=dec_b, 5=k (fixed 256)
//   output: [output (8192*256) | hidden_post (8192*16384)] fp32
// ---------------------------------------------------------------------------
extern "C" void kernel_launch(void* const* d_in, const int* in_sizes, int n_in,
                              void* d_out, int out_size) {
    const float* x     = (const float*)d_in[0];
    const float* enc_w = (const float*)d_in[1];
    const float* enc_b = (const float*)d_in[2];
    const float* dec_w = (const float*)d_in[3];
    const float* dec_b = (const float*)d_in[4];

    float* out = (float*)d_out;
    float* hid = out + (size_t)BATCH * OUT_DIM;

    // idempotent attribute setup (host-side, not captured)
    cudaFuncSetAttribute(fused_topk_decode_kernel,
                         cudaFuncAttributeMaxDynamicSharedMemorySize,
                         (int)sizeof(FusedSmem));
    cudaFuncSetAttribute(gemm_mma_kernel,
                         cudaFuncAttributeMaxDynamicSharedMemorySize,
                         GEMM_SMEM);

    // prep: 2-way bf16 splits of x and enc_w; dec_w transpose
    split_x_kernel<<<(BATCH * IN_DIM + 255) / 256, 256>>>(x);
    split_w_kernel<<<(HID_DIM * IN_DIM + 255) / 256, 256>>>(enc_w);
    transpose_kernel<<<dim3(HID_DIM / 32, OUT_DIM / 32), dim3(32, 8)>>>(dec_w);

    // k1: HMMA bf16 2-split / 3-product encoder GEMM + bias + relu
    gemm_mma_kernel<<<dim3(HID_DIM / 128, BATCH / 128), 256, GEMM_SMEM>>>(enc_b, hid);

    // k2: fused top-k (list-based histogram radix) + band recheck + decode
    fused_topk_decode_kernel<<<BATCH, 256, sizeof(FusedSmem)>>>(
        hid, x, enc_w, enc_b, dec_b, out);
}